// round 2
// baseline (speedup 1.0000x reference)
#include <cuda_runtime.h>
#include <math.h>

#define NT      262144      // total nodes (512 subgraphs x 512 nodes)
#define NN      512         // nodes per subgraph / original graph
#define E_SUB   2097152     // edges in union-of-subgraphs graph
#define EO      8192        // edges in original graph
#define D       64          // emb dim
#define LAYERS  4
#define GP      136         // smem pitch (words)

typedef unsigned long long ull;

// ------------------------- device scratch (no cudaMalloc allowed) ----------
__device__ __align__(16) float g_hA[(size_t)NT * D];
__device__ __align__(16) float g_hB[(size_t)NT * D];
__device__ __align__(16) float g_agg[(size_t)NT * D];

__device__ __align__(16) float g_xsum[NN * D];
__device__ __align__(16) float g_aggs[NN * D];
__device__ __align__(16) float g_y2[NN * D];

__device__ __align__(16) float g_stA[2 * D];
__device__ __align__(16) float g_stS[2 * D];
__device__ __align__(16) float g_scale[D],  g_shift[D];
__device__ __align__(16) float g_scale_s[D], g_shift_s[D];

__device__ int g_cnt[NT];
__device__ int g_rowptr[NT + 1];
__device__ int g_bsum[256];
__device__ int g_csrsrc[E_SUB];

// ------------------------- packed f32x2 FMA ---------------------------------
__device__ __forceinline__ ull fma2(ull a, ull b, ull c) {
    ull d;
    asm("fma.rn.f32x2 %0, %1, %2, %3;" : "=l"(d) : "l"(a), "l"(b), "l"(c));
    return d;
}

// ------------------------- CSR build ---------------------------------------
__global__ void k_hist(const int* __restrict__ dst) {
    int e = blockIdx.x * blockDim.x + threadIdx.x;
    if (e < E_SUB) atomicAdd(&g_cnt[dst[e]], 1);
}

__global__ void k_bsum() {
    __shared__ int sh[256];
    int b = blockIdx.x, t = threadIdx.x;
    int base = b * 1024 + t * 4;
    int v = g_cnt[base] + g_cnt[base + 1] + g_cnt[base + 2] + g_cnt[base + 3];
    sh[t] = v;
    __syncthreads();
    for (int off = 128; off > 0; off >>= 1) {
        if (t < off) sh[t] += sh[t + off];
        __syncthreads();
    }
    if (t == 0) g_bsum[b] = sh[0];
}

__global__ void k_scanb() {
    __shared__ int sh[256];
    int t = threadIdx.x;
    int orig = g_bsum[t];
    sh[t] = orig;
    __syncthreads();
    for (int off = 1; off < 256; off <<= 1) {
        int v = (t >= off) ? sh[t - off] : 0;
        __syncthreads();
        sh[t] += v;
        __syncthreads();
    }
    g_bsum[t] = sh[t] - orig;   // exclusive
}

__global__ void k_scanlocal() {
    __shared__ int sh[256];
    int b = blockIdx.x, t = threadIdx.x;
    int base = (b * 256 + t) * 4;
    int c0 = g_cnt[base], c1 = g_cnt[base + 1], c2 = g_cnt[base + 2], c3 = g_cnt[base + 3];
    int tsum = c0 + c1 + c2 + c3;
    sh[t] = tsum;
    __syncthreads();
    for (int off = 1; off < 256; off <<= 1) {
        int v = (t >= off) ? sh[t - off] : 0;
        __syncthreads();
        sh[t] += v;
        __syncthreads();
    }
    int excl = sh[t] - tsum + g_bsum[b];
    int e0 = excl, e1 = e0 + c0, e2 = e1 + c1, e3 = e2 + c2;
    g_rowptr[base] = e0; g_rowptr[base + 1] = e1;
    g_rowptr[base + 2] = e2; g_rowptr[base + 3] = e3;
    g_cnt[base] = e0; g_cnt[base + 1] = e1;
    g_cnt[base + 2] = e2; g_cnt[base + 3] = e3;
    if (b == 255 && t == 255) g_rowptr[NT] = E_SUB;
}

__global__ void k_scatter(const int* __restrict__ src, const int* __restrict__ dst) {
    int e = blockIdx.x * blockDim.x + threadIdx.x;
    if (e < E_SUB) {
        int pos = atomicAdd(&g_cnt[dst[e]], 1);
        g_csrsrc[pos] = src[e];
    }
}

// ------------------------- edge aggregation (atomic-free, float2) ----------
__global__ void k_gather(const float* __restrict__ h) {
    int gw = (blockIdx.x * blockDim.x + threadIdx.x) >> 5;
    int lane = threadIdx.x & 31;
    if (gw >= NT) return;
    int s = g_rowptr[gw], e = g_rowptr[gw + 1];
    float2 a = make_float2(0.f, 0.f), b = make_float2(0.f, 0.f);
    int i = s;
    for (; i + 1 < e; i += 2) {
        int s0 = g_csrsrc[i], s1 = g_csrsrc[i + 1];
        float2 v0 = reinterpret_cast<const float2*>(h)[(size_t)s0 * 32 + lane];
        float2 v1 = reinterpret_cast<const float2*>(h)[(size_t)s1 * 32 + lane];
        a.x += v0.x; a.y += v0.y;
        b.x += v1.x; b.y += v1.y;
    }
    if (i < e) {
        int s0 = g_csrsrc[i];
        float2 v0 = reinterpret_cast<const float2*>(h)[(size_t)s0 * 32 + lane];
        a.x += v0.x; a.y += v0.y;
    }
    reinterpret_cast<float2*>(g_agg)[(size_t)gw * 32 + lane] =
        make_float2(a.x + b.x, a.y + b.y);
}

// ------------------------- dual GEMM, f32x2, fused BN stats ----------------
// Y[r][c] = sum_k A0[r][k]*W0[c][k] + A1[r][k]*W1[c][k] + bias[c]
// 128 threads, block tile 128 rows x 64 cols, per-thread 8x8.
// Accumulators pack row pairs; W duplicated in smem so both FMA2 operands are
// natural 16B-aligned pairs (zero pack instructions).
__global__ void __launch_bounds__(128)
k_gemm2(const float* __restrict__ A0, const float* __restrict__ A1,
        const float* __restrict__ W0, const float* __restrict__ W1v,
        const float* __restrict__ bias, float* __restrict__ Y,
        float* __restrict__ st) {
    __shared__ __align__(16) float sA[32][GP];    // sA[k][row]
    __shared__ __align__(16) float sBd[32][GP];   // sBd[k][2c]=sBd[k][2c+1]=W[c][k]
    int t  = threadIdx.x;
    int tx = t & 7;          // col group: cols tx*8 .. tx*8+7
    int ty = t >> 3;         // row group: rows ty*8 .. ty*8+7
    int row0 = blockIdx.x * 128;

    ull acc[4][8];           // [row-pair][col]
#pragma unroll
    for (int i = 0; i < 4; i++)
#pragma unroll
        for (int j = 0; j < 8; j++) acc[i][j] = 0ULL;

    for (int p = 0; p < 2; p++) {
        const float* A = p ? A1 : A0;
        const float* W = p ? W1v : W0;
        for (int kk = 0; kk < 2; kk++) {
            int kbase = kk * 32;
            __syncthreads();
            // load A chunk: 128 rows x 32 k, transposed into sA[k][row]
#pragma unroll
            for (int it = 0; it < 8; it++) {
                int idx4 = it * 128 + t;
                int c4 = idx4 & 7;            // float4 index within 32 k
                int r  = idx4 >> 3;           // row 0..127
                float4 v = *reinterpret_cast<const float4*>(
                    &A[(size_t)(row0 + r) * D + kbase + c4 * 4]);
                sA[c4 * 4 + 0][r] = v.x;
                sA[c4 * 4 + 1][r] = v.y;
                sA[c4 * 4 + 2][r] = v.z;
                sA[c4 * 4 + 3][r] = v.w;
            }
            // load W chunk duplicated: sBd[k][2c],[2c+1] = W[c][kbase+k]
#pragma unroll
            for (int it = 0; it < 4; it++) {
                int idx4 = it * 128 + t;
                int c4 = idx4 & 7;
                int c  = idx4 >> 3;           // out col 0..63
                float4 v = *reinterpret_cast<const float4*>(
                    &W[c * D + kbase + c4 * 4]);
                int k0 = c4 * 4;
                sBd[k0 + 0][2 * c] = v.x; sBd[k0 + 0][2 * c + 1] = v.x;
                sBd[k0 + 1][2 * c] = v.y; sBd[k0 + 1][2 * c + 1] = v.y;
                sBd[k0 + 2][2 * c] = v.z; sBd[k0 + 2][2 * c + 1] = v.z;
                sBd[k0 + 3][2 * c] = v.w; sBd[k0 + 3][2 * c + 1] = v.w;
            }
            __syncthreads();
#pragma unroll 8
            for (int k = 0; k < 32; k++) {
                const ulonglong2* ap = reinterpret_cast<const ulonglong2*>(&sA[k][ty * 8]);
                ulonglong2 av0 = ap[0], av1 = ap[1];
                ull a0 = av0.x, a1 = av0.y, a2 = av1.x, a3 = av1.y;
                const ulonglong2* bp = reinterpret_cast<const ulonglong2*>(&sBd[k][tx * 16]);
                ulonglong2 bv0 = bp[0], bv1 = bp[1], bv2 = bp[2], bv3 = bp[3];
                ull b[8] = { bv0.x, bv0.y, bv1.x, bv1.y, bv2.x, bv2.y, bv3.x, bv3.y };
#pragma unroll
                for (int j = 0; j < 8; j++) {
                    acc[0][j] = fma2(a0, b[j], acc[0][j]);
                    acc[1][j] = fma2(a1, b[j], acc[1][j]);
                    acc[2][j] = fma2(a2, b[j], acc[2][j]);
                    acc[3][j] = fma2(a3, b[j], acc[3][j]);
                }
            }
        }
    }

    // epilogue: unpack, add bias, write, and accumulate BN stats
    float bcol[8];
#pragma unroll
    for (int j = 0; j < 8; j++) bcol[j] = bias[tx * 8 + j];

    float ls[8], lq[8];
#pragma unroll
    for (int j = 0; j < 8; j++) { ls[j] = 0.f; lq[j] = 0.f; }

    union U { ull u; float2 f; };
#pragma unroll
    for (int i2 = 0; i2 < 4; i2++) {
        float ylo[8], yhi[8];
#pragma unroll
        for (int j = 0; j < 8; j++) {
            U v; v.u = acc[i2][j];
            float lo = v.f.x + bcol[j];
            float hi = v.f.y + bcol[j];
            ylo[j] = lo; yhi[j] = hi;
            ls[j] += lo + hi;
            lq[j] += lo * lo + hi * hi;
        }
        size_t rlo = (size_t)(row0 + ty * 8 + 2 * i2) * D + tx * 8;
        *reinterpret_cast<float4*>(&Y[rlo])     = make_float4(ylo[0], ylo[1], ylo[2], ylo[3]);
        *reinterpret_cast<float4*>(&Y[rlo + 4]) = make_float4(ylo[4], ylo[5], ylo[6], ylo[7]);
        *reinterpret_cast<float4*>(&Y[rlo + D])     = make_float4(yhi[0], yhi[1], yhi[2], yhi[3]);
        *reinterpret_cast<float4*>(&Y[rlo + D + 4]) = make_float4(yhi[4], yhi[5], yhi[6], yhi[7]);
    }

    // block reduction of column sums / sumsq (reuse smem)
    __syncthreads();
    float* rs = &sA[0][0];    // [16][64]
    float* rq = &sBd[0][0];
#pragma unroll
    for (int j = 0; j < 8; j++) {
        rs[ty * 64 + tx * 8 + j] = ls[j];
        rq[ty * 64 + tx * 8 + j] = lq[j];
    }
    __syncthreads();
    if (t < 64) {
        float s = 0.f, q = 0.f;
#pragma unroll
        for (int g = 0; g < 16; g++) {
            s += rs[g * 64 + t];
            q += rq[g * 64 + t];
        }
        atomicAdd(&st[t], s);
        atomicAdd(&st[64 + t], q);
    }
}

// ------------------------- BN finalize --------------------------------------
__global__ void k_finalize(const float* __restrict__ st,
                           const float* __restrict__ gamma, const float* __restrict__ beta,
                           float inv, float* __restrict__ scale, float* __restrict__ shift) {
    int t = threadIdx.x;
    float mean = st[t] * inv;
    float var  = st[64 + t] * inv - mean * mean;
    float is   = rsqrtf(var + 1e-5f);
    float sc   = gamma[t] * is;
    scale[t] = sc;
    shift[t] = beta[t] - mean * sc;
}

// ------------------------- subgraph mean (x_sum) ----------------------------
__global__ void k_xsum_partial(const float* __restrict__ h) {
    int n  = blockIdx.x & (NN - 1);
    int sg = blockIdx.x >> 9;
    int c  = threadIdx.x;
    float a0 = 0.f, a1 = 0.f, a2 = 0.f, a3 = 0.f;
#pragma unroll 4
    for (int j = 0; j < 64; j += 4) {
        int s = sg * 64 + j;
        a0 += h[((size_t)(s + 0) * NN + n) * D + c];
        a1 += h[((size_t)(s + 1) * NN + n) * D + c];
        a2 += h[((size_t)(s + 2) * NN + n) * D + c];
        a3 += h[((size_t)(s + 3) * NN + n) * D + c];
    }
    atomicAdd(&g_xsum[n * D + c], (a0 + a1 + a2 + a3) * (1.0f / 512.0f));
}

// ------------------------- small graph scatter ------------------------------
__global__ void k_scatter_s(const int* __restrict__ src, const int* __restrict__ dst) {
    int t = blockIdx.x * blockDim.x + threadIdx.x;
    int e = t >> 6, c = t & 63;
    if (e < EO) atomicAdd(&g_aggs[dst[e] * D + c], g_xsum[src[e] * D + c]);
}

// ------------------------- combine: h = relu(BN1(y) + BN2(y2)[n]) ----------
__global__ void k_combine(float* __restrict__ Y) {
    int i4 = blockIdx.x * blockDim.x + threadIdx.x;     // < NT*16
    int r = i4 >> 4, q = i4 & 15;
    int n = r & (NN - 1);
    int cb = q * 4;
    float4 y   = reinterpret_cast<float4*>(Y)[i4];
    float4 sc  = *reinterpret_cast<const float4*>(&g_scale[cb]);
    float4 sf  = *reinterpret_cast<const float4*>(&g_shift[cb]);
    float4 scs = *reinterpret_cast<const float4*>(&g_scale_s[cb]);
    float4 sfs = *reinterpret_cast<const float4*>(&g_shift_s[cb]);
    float4 y2  = *reinterpret_cast<const float4*>(&g_y2[n * D + cb]);
    y.x = fmaxf(y.x * sc.x + sf.x + y2.x * scs.x + sfs.x, 0.f);
    y.y = fmaxf(y.y * sc.y + sf.y + y2.y * scs.y + sfs.y, 0.f);
    y.z = fmaxf(y.z * sc.z + sf.z + y2.z * scs.z + sfs.z, 0.f);
    y.w = fmaxf(y.w * sc.w + sf.w + y2.w * scs.w + sfs.w, 0.f);
    reinterpret_cast<float4*>(Y)[i4] = y;
}

// ------------------------- final head: log_softmax + MLP -------------------
__global__ void k_final(const float* __restrict__ W1, const float* __restrict__ b1,
                        const float* __restrict__ W2, const float* __restrict__ b2,
                        float* __restrict__ out) {
    __shared__ float z[64];
    __shared__ float hid[128];
    __shared__ float red[2];
    int n = blockIdx.x, t = threadIdx.x;
    if (t < 64) z[t] = g_xsum[n * D + t];
    __syncthreads();
    if (t == 0) {
        float m = -1e30f;
        for (int k = 0; k < 64; k++) m = fmaxf(m, z[k]);
        float se = 0.f;
        for (int k = 0; k < 64; k++) se += expf(z[k] - m);
        red[0] = m;
        red[1] = logf(se);
    }
    __syncthreads();
    float m = red[0], ls = red[1];
    float acc = b1[t];
    for (int k = 0; k < 64; k++) acc += (z[k] - m - ls) * W1[t * 64 + k];
    hid[t] = fmaxf(acc, 0.f);
    __syncthreads();
    if (t < 10) {
        float o = b2[t];
        for (int k = 0; k < 128; k++) o += hid[k] * W2[t * 128 + k];
        out[n * 10 + t] = o;
    }
}

// ------------------------- launcher -----------------------------------------
extern "C" void kernel_launch(void* const* d_in, const int* in_sizes, int n_in,
                              void* d_out, int out_size) {
    const float* x      = (const float*)d_in[0];
    const float* Wrel   = (const float*)d_in[1];
    const float* brel   = (const float*)d_in[2];
    const float* Wroot  = (const float*)d_in[3];
    const float* bng    = (const float*)d_in[4];
    const float* bnb    = (const float*)d_in[5];
    const float* Wrel_s = (const float*)d_in[6];
    const float* brel_s = (const float*)d_in[7];
    const float* Wroot_s= (const float*)d_in[8];
    const float* bnsg   = (const float*)d_in[9];
    const float* bnsb   = (const float*)d_in[10];
    const float* W1     = (const float*)d_in[11];
    const float* b1     = (const float*)d_in[12];
    const float* W2     = (const float*)d_in[13];
    const float* b2     = (const float*)d_in[14];
    const int*   ei     = (const int*)d_in[15];
    const int*   oe     = (const int*)d_in[16];
    float*       out    = (float*)d_out;

    void *p_cnt, *p_hA, *p_hB, *p_agg, *p_xsum, *p_aggs, *p_y2;
    void *p_stA, *p_stS, *p_scale, *p_shift, *p_scale_s, *p_shift_s;
    cudaGetSymbolAddress(&p_cnt, g_cnt);
    cudaGetSymbolAddress(&p_hA, g_hA);
    cudaGetSymbolAddress(&p_hB, g_hB);
    cudaGetSymbolAddress(&p_agg, g_agg);
    cudaGetSymbolAddress(&p_xsum, g_xsum);
    cudaGetSymbolAddress(&p_aggs, g_aggs);
    cudaGetSymbolAddress(&p_y2, g_y2);
    cudaGetSymbolAddress(&p_stA, g_stA);
    cudaGetSymbolAddress(&p_stS, g_stS);
    cudaGetSymbolAddress(&p_scale, g_scale);
    cudaGetSymbolAddress(&p_shift, g_shift);
    cudaGetSymbolAddress(&p_scale_s, g_scale_s);
    cudaGetSymbolAddress(&p_shift_s, g_shift_s);

    // ---- CSR build ----
    cudaMemsetAsync(p_cnt, 0, NT * sizeof(int));
    k_hist<<<E_SUB / 256, 256>>>(ei + E_SUB);
    k_bsum<<<256, 256>>>();
    k_scanb<<<1, 256>>>();
    k_scanlocal<<<256, 256>>>();
    k_scatter<<<E_SUB / 256, 256>>>(ei, ei + E_SUB);

    const float* hcur = x;
    float* bufs[2] = { (float*)p_hA, (float*)p_hB };

    for (int i = 0; i < LAYERS; i++) {
        float* Y = bufs[i & 1];

        // big-graph path: aggregation + dual GEMM (stats fused)
        k_gather<<<(NT * 32) / 256, 256>>>(hcur);
        cudaMemsetAsync(p_stA, 0, 2 * D * sizeof(float));
        k_gemm2<<<NT / 128, 128>>>((const float*)p_agg, hcur,
                                   Wrel + i * 4096, Wroot + i * 4096, brel + i * 64,
                                   Y, (float*)p_stA);
        k_finalize<<<1, 64>>>((const float*)p_stA, bng + i * 64, bnb + i * 64,
                              1.0f / (float)NT, (float*)p_scale, (float*)p_shift);

        // subgraph-level path
        cudaMemsetAsync(p_xsum, 0, NN * D * sizeof(float));
        k_xsum_partial<<<NN * 8, 64>>>(hcur);
        cudaMemsetAsync(p_aggs, 0, NN * D * sizeof(float));
        k_scatter_s<<<(EO * 64) / 256, 256>>>(oe, oe + EO);
        cudaMemsetAsync(p_stS, 0, 2 * D * sizeof(float));
        k_gemm2<<<NN / 128, 128>>>((const float*)p_aggs, (const float*)p_xsum,
                                   Wrel_s + i * 4096, Wroot_s + i * 4096, brel_s + i * 64,
                                   (float*)p_y2, (float*)p_stS);
        k_finalize<<<1, 64>>>((const float*)p_stS, bnsg + i * 64, bnsb + i * 64,
                              1.0f / (float)NN, (float*)p_scale_s, (float*)p_shift_s);

        // fuse both BNs + broadcast + relu, in place
        k_combine<<<(NT * 16) / 256, 256>>>(Y);
        hcur = Y;
    }

    // readout: subgraph mean -> log_softmax -> MLP
    cudaMemsetAsync(p_xsum, 0, NN * D * sizeof(float));
    k_xsum_partial<<<NN * 8, 64>>>(hcur);
    k_final<<<NN, 128>>>(W1, b1, W2, b2, out);
}

// round 3
// speedup vs baseline: 1.4699x; 1.4699x over previous
#include <cuda_runtime.h>
#include <math.h>

#define NT      262144      // total nodes (512 subgraphs x 512 nodes)
#define NN      512         // nodes per subgraph / original graph
#define E_SUB   2097152     // edges in union-of-subgraphs graph
#define EO      8192        // edges in original graph
#define D       64          // emb dim
#define LAYERS  4
#define GP      132         // smem pitch (words): even (8B pair alignment), 132*4%16==0

typedef unsigned long long ull;

// ------------------------- device scratch (no cudaMalloc allowed) ----------
__device__ __align__(16) float g_hA[(size_t)NT * D];
__device__ __align__(16) float g_hB[(size_t)NT * D];
__device__ __align__(16) float g_agg[(size_t)NT * D];

__device__ __align__(16) float g_xsum[NN * D];
__device__ __align__(16) float g_aggs[NN * D];
__device__ __align__(16) float g_y2[NN * D];

__device__ __align__(16) float g_stA[2 * D];
__device__ __align__(16) float g_stS[2 * D];
__device__ __align__(16) float g_scale[D],  g_shift[D];
__device__ __align__(16) float g_scale_s[D], g_shift_s[D];

__device__ int g_cnt[NT];
__device__ int g_rowptr[NT + 1];
__device__ int g_bsum[256];
__device__ int g_csrsrc[E_SUB];

// ------------------------- packed f32x2 FMA ---------------------------------
__device__ __forceinline__ ull fma2(ull a, ull b, ull c) {
    ull d;
    asm("fma.rn.f32x2 %0, %1, %2, %3;" : "=l"(d) : "l"(a), "l"(b), "l"(c));
    return d;
}

// ------------------------- CSR build ---------------------------------------
__global__ void k_hist(const int* __restrict__ dst) {
    int e = blockIdx.x * blockDim.x + threadIdx.x;
    if (e < E_SUB) atomicAdd(&g_cnt[dst[e]], 1);
}

__global__ void k_bsum() {
    __shared__ int sh[256];
    int b = blockIdx.x, t = threadIdx.x;
    int base = b * 1024 + t * 4;
    int v = g_cnt[base] + g_cnt[base + 1] + g_cnt[base + 2] + g_cnt[base + 3];
    sh[t] = v;
    __syncthreads();
    for (int off = 128; off > 0; off >>= 1) {
        if (t < off) sh[t] += sh[t + off];
        __syncthreads();
    }
    if (t == 0) g_bsum[b] = sh[0];
}

__global__ void k_scanb() {
    __shared__ int sh[256];
    int t = threadIdx.x;
    int orig = g_bsum[t];
    sh[t] = orig;
    __syncthreads();
    for (int off = 1; off < 256; off <<= 1) {
        int v = (t >= off) ? sh[t - off] : 0;
        __syncthreads();
        sh[t] += v;
        __syncthreads();
    }
    g_bsum[t] = sh[t] - orig;   // exclusive
}

__global__ void k_scanlocal() {
    __shared__ int sh[256];
    int b = blockIdx.x, t = threadIdx.x;
    int base = (b * 256 + t) * 4;
    int c0 = g_cnt[base], c1 = g_cnt[base + 1], c2 = g_cnt[base + 2], c3 = g_cnt[base + 3];
    int tsum = c0 + c1 + c2 + c3;
    sh[t] = tsum;
    __syncthreads();
    for (int off = 1; off < 256; off <<= 1) {
        int v = (t >= off) ? sh[t - off] : 0;
        __syncthreads();
        sh[t] += v;
        __syncthreads();
    }
    int excl = sh[t] - tsum + g_bsum[b];
    int e0 = excl, e1 = e0 + c0, e2 = e1 + c1, e3 = e2 + c2;
    g_rowptr[base] = e0; g_rowptr[base + 1] = e1;
    g_rowptr[base + 2] = e2; g_rowptr[base + 3] = e3;
    g_cnt[base] = e0; g_cnt[base + 1] = e1;
    g_cnt[base + 2] = e2; g_cnt[base + 3] = e3;
    if (b == 255 && t == 255) g_rowptr[NT] = E_SUB;
}

__global__ void k_scatter(const int* __restrict__ src, const int* __restrict__ dst) {
    int e = blockIdx.x * blockDim.x + threadIdx.x;
    if (e < E_SUB) {
        int pos = atomicAdd(&g_cnt[dst[e]], 1);
        g_csrsrc[pos] = src[e];
    }
}

// ------------------------- edge aggregation (atomic-free, float2) ----------
__global__ void k_gather(const float* __restrict__ h) {
    int gw = (blockIdx.x * blockDim.x + threadIdx.x) >> 5;
    int lane = threadIdx.x & 31;
    if (gw >= NT) return;
    int s = g_rowptr[gw], e = g_rowptr[gw + 1];
    float2 a = make_float2(0.f, 0.f), b = make_float2(0.f, 0.f);
    int i = s;
    for (; i + 1 < e; i += 2) {
        int s0 = g_csrsrc[i], s1 = g_csrsrc[i + 1];
        float2 v0 = reinterpret_cast<const float2*>(h)[(size_t)s0 * 32 + lane];
        float2 v1 = reinterpret_cast<const float2*>(h)[(size_t)s1 * 32 + lane];
        a.x += v0.x; a.y += v0.y;
        b.x += v1.x; b.y += v1.y;
    }
    if (i < e) {
        int s0 = g_csrsrc[i];
        float2 v0 = reinterpret_cast<const float2*>(h)[(size_t)s0 * 32 + lane];
        a.x += v0.x; a.y += v0.y;
    }
    reinterpret_cast<float2*>(g_agg)[(size_t)gw * 32 + lane] =
        make_float2(a.x + b.x, a.y + b.y);
}

// ------------------------- dual GEMM, f32x2 rev2, fused BN stats ------------
// Y[r][c] = sum_k A0[r][k]*W0[c][k] + A1[r][k]*W1[c][k] + bias[c]
// 256 threads, block tile 128 rows x 64 cols, per-thread 4 row-pairs x 4 cols.
// acc[4][4] ull = 32 regs only. B duplicated pairs in split-half layout so
// every LDS.128 warp footprint is contiguous (<=2 wavefronts).
__global__ void __launch_bounds__(256)
k_gemm2p(const float* __restrict__ A0, const float* __restrict__ A1,
         const float* __restrict__ W0, const float* __restrict__ W1v,
         const float* __restrict__ bias, float* __restrict__ Y,
         float* __restrict__ st) {
    __shared__ __align__(16) float sA[64][GP];    // sA[k][row]
    __shared__ __align__(16) float sBd[64][GP];   // dup pairs, split-half layout
    int t  = threadIdx.x;
    int tx = t & 15;          // col group: cols tx*4 .. tx*4+3
    int ty = t >> 4;          // row group: rows ty*8 .. ty*8+7 (4 pairs)
    int row0 = blockIdx.x * 128;

    ull acc[4][4];
#pragma unroll
    for (int i = 0; i < 4; i++)
#pragma unroll
        for (int j = 0; j < 4; j++) acc[i][j] = 0ULL;

    for (int p = 0; p < 2; p++) {
        const float* A = p ? A1 : A0;
        const float* W = p ? W1v : W0;
        __syncthreads();
        // A fill: 128 rows x 64 k, transposed to sA[k][row]
#pragma unroll
        for (int it = 0; it < 8; it++) {
            int idx = it * 256 + t;
            int c4 = idx & 15;            // float4 index along k
            int r  = idx >> 4;            // row 0..127
            float4 v = *reinterpret_cast<const float4*>(&A[(size_t)(row0 + r) * D + c4 * 4]);
            sA[c4 * 4 + 0][r] = v.x;
            sA[c4 * 4 + 1][r] = v.y;
            sA[c4 * 4 + 2][r] = v.z;
            sA[c4 * 4 + 3][r] = v.w;
        }
        // B fill: col c, k -> dup pair (8B) at word w(c):
        //   s=c&3: s0 -> w=(c>>2)*4,  s1 -> +2,  s2 -> 64+(c>>2)*4,  s3 -> 64+..+2
#pragma unroll
        for (int it = 0; it < 4; it++) {
            int idx = it * 256 + t;
            int k4 = idx & 15;
            int c  = idx >> 4;            // out col 0..63
            float4 v = *reinterpret_cast<const float4*>(&W[c * D + k4 * 4]);
            int w = ((c & 2) ? 64 : 0) + (c >> 2) * 4 + (c & 1) * 2;
            *reinterpret_cast<float2*>(&sBd[k4 * 4 + 0][w]) = make_float2(v.x, v.x);
            *reinterpret_cast<float2*>(&sBd[k4 * 4 + 1][w]) = make_float2(v.y, v.y);
            *reinterpret_cast<float2*>(&sBd[k4 * 4 + 2][w]) = make_float2(v.z, v.z);
            *reinterpret_cast<float2*>(&sBd[k4 * 4 + 3][w]) = make_float2(v.w, v.w);
        }
        __syncthreads();
#pragma unroll 8
        for (int k = 0; k < 64; k++) {
            ulonglong2 av0 = *reinterpret_cast<const ulonglong2*>(&sA[k][ty * 8]);
            ulonglong2 av1 = *reinterpret_cast<const ulonglong2*>(&sA[k][ty * 8 + 4]);
            ulonglong2 bv0 = *reinterpret_cast<const ulonglong2*>(&sBd[k][tx * 4]);
            ulonglong2 bv1 = *reinterpret_cast<const ulonglong2*>(&sBd[k][64 + tx * 4]);
            ull a0 = av0.x, a1 = av0.y, a2 = av1.x, a3 = av1.y;
            ull b0 = bv0.x, b1 = bv0.y, b2 = bv1.x, b3 = bv1.y;
            acc[0][0] = fma2(a0, b0, acc[0][0]);
            acc[0][1] = fma2(a0, b1, acc[0][1]);
            acc[0][2] = fma2(a0, b2, acc[0][2]);
            acc[0][3] = fma2(a0, b3, acc[0][3]);
            acc[1][0] = fma2(a1, b0, acc[1][0]);
            acc[1][1] = fma2(a1, b1, acc[1][1]);
            acc[1][2] = fma2(a1, b2, acc[1][2]);
            acc[1][3] = fma2(a1, b3, acc[1][3]);
            acc[2][0] = fma2(a2, b0, acc[2][0]);
            acc[2][1] = fma2(a2, b1, acc[2][1]);
            acc[2][2] = fma2(a2, b2, acc[2][2]);
            acc[2][3] = fma2(a2, b3, acc[2][3]);
            acc[3][0] = fma2(a3, b0, acc[3][0]);
            acc[3][1] = fma2(a3, b1, acc[3][1]);
            acc[3][2] = fma2(a3, b2, acc[3][2]);
            acc[3][3] = fma2(a3, b3, acc[3][3]);
        }
    }

    // epilogue: unpack pairs, add bias, write Y, accumulate BN stats
    float bcol[4];
#pragma unroll
    for (int j = 0; j < 4; j++) bcol[j] = bias[tx * 4 + j];

    float ls[4], lq[4];
#pragma unroll
    for (int j = 0; j < 4; j++) { ls[j] = 0.f; lq[j] = 0.f; }

    union U { ull u; float2 f; };
#pragma unroll
    for (int i = 0; i < 4; i++) {
        float ylo[4], yhi[4];
#pragma unroll
        for (int j = 0; j < 4; j++) {
            U v; v.u = acc[i][j];
            float lo = v.f.x + bcol[j];   // row ty*8+2i
            float hi = v.f.y + bcol[j];   // row ty*8+2i+1
            ylo[j] = lo; yhi[j] = hi;
            ls[j] += lo + hi;
            lq[j] += lo * lo + hi * hi;
        }
        size_t rlo = (size_t)(row0 + ty * 8 + 2 * i) * D + tx * 4;
        *reinterpret_cast<float4*>(&Y[rlo])     = make_float4(ylo[0], ylo[1], ylo[2], ylo[3]);
        *reinterpret_cast<float4*>(&Y[rlo + D]) = make_float4(yhi[0], yhi[1], yhi[2], yhi[3]);
    }

    // block reduction of column sums / sumsq (reuse sA)
    __syncthreads();
    float* rs = &sA[0][0];
    float* rq = &sA[32][0];
#pragma unroll
    for (int j = 0; j < 4; j++) {
        rs[ty * 64 + tx * 4 + j] = ls[j];
        rq[ty * 64 + tx * 4 + j] = lq[j];
    }
    __syncthreads();
    if (t < 64) {
        float s = 0.f, q = 0.f;
#pragma unroll
        for (int g = 0; g < 16; g++) {
            s += rs[g * 64 + t];
            q += rq[g * 64 + t];
        }
        atomicAdd(&st[t], s);
        atomicAdd(&st[64 + t], q);
    }
}

// ------------------------- BN finalize --------------------------------------
__global__ void k_finalize(const float* __restrict__ st,
                           const float* __restrict__ gamma, const float* __restrict__ beta,
                           float inv, float* __restrict__ scale, float* __restrict__ shift) {
    int t = threadIdx.x;
    float mean = st[t] * inv;
    float var  = st[64 + t] * inv - mean * mean;
    float is   = rsqrtf(var + 1e-5f);
    float sc   = gamma[t] * is;
    scale[t] = sc;
    shift[t] = beta[t] - mean * sc;
}

// ------------------------- subgraph mean (x_sum) ----------------------------
__global__ void k_xsum_partial(const float* __restrict__ h) {
    int n  = blockIdx.x & (NN - 1);
    int sg = blockIdx.x >> 9;
    int c  = threadIdx.x;
    float a0 = 0.f, a1 = 0.f, a2 = 0.f, a3 = 0.f;
#pragma unroll 4
    for (int j = 0; j < 64; j += 4) {
        int s = sg * 64 + j;
        a0 += h[((size_t)(s + 0) * NN + n) * D + c];
        a1 += h[((size_t)(s + 1) * NN + n) * D + c];
        a2 += h[((size_t)(s + 2) * NN + n) * D + c];
        a3 += h[((size_t)(s + 3) * NN + n) * D + c];
    }
    atomicAdd(&g_xsum[n * D + c], (a0 + a1 + a2 + a3) * (1.0f / 512.0f));
}

// ------------------------- small graph scatter ------------------------------
__global__ void k_scatter_s(const int* __restrict__ src, const int* __restrict__ dst) {
    int t = blockIdx.x * blockDim.x + threadIdx.x;
    int e = t >> 6, c = t & 63;
    if (e < EO) atomicAdd(&g_aggs[dst[e] * D + c], g_xsum[src[e] * D + c]);
}

// ------------------------- combine: h = relu(BN1(y) + BN2(y2)[n]) ----------
__global__ void k_combine(float* __restrict__ Y) {
    int i4 = blockIdx.x * blockDim.x + threadIdx.x;     // < NT*16
    int r = i4 >> 4, q = i4 & 15;
    int n = r & (NN - 1);
    int cb = q * 4;
    float4 y   = reinterpret_cast<float4*>(Y)[i4];
    float4 sc  = *reinterpret_cast<const float4*>(&g_scale[cb]);
    float4 sf  = *reinterpret_cast<const float4*>(&g_shift[cb]);
    float4 scs = *reinterpret_cast<const float4*>(&g_scale_s[cb]);
    float4 sfs = *reinterpret_cast<const float4*>(&g_shift_s[cb]);
    float4 y2  = *reinterpret_cast<const float4*>(&g_y2[n * D + cb]);
    y.x = fmaxf(y.x * sc.x + sf.x + y2.x * scs.x + sfs.x, 0.f);
    y.y = fmaxf(y.y * sc.y + sf.y + y2.y * scs.y + sfs.y, 0.f);
    y.z = fmaxf(y.z * sc.z + sf.z + y2.z * scs.z + sfs.z, 0.f);
    y.w = fmaxf(y.w * sc.w + sf.w + y2.w * scs.w + sfs.w, 0.f);
    reinterpret_cast<float4*>(Y)[i4] = y;
}

// ------------------------- final head: log_softmax + MLP -------------------
__global__ void k_final(const float* __restrict__ W1, const float* __restrict__ b1,
                        const float* __restrict__ W2, const float* __restrict__ b2,
                        float* __restrict__ out) {
    __shared__ float z[64];
    __shared__ float hid[128];
    __shared__ float red[2];
    int n = blockIdx.x, t = threadIdx.x;
    if (t < 64) z[t] = g_xsum[n * D + t];
    __syncthreads();
    if (t == 0) {
        float m = -1e30f;
        for (int k = 0; k < 64; k++) m = fmaxf(m, z[k]);
        float se = 0.f;
        for (int k = 0; k < 64; k++) se += expf(z[k] - m);
        red[0] = m;
        red[1] = logf(se);
    }
    __syncthreads();
    float m = red[0], ls = red[1];
    float acc = b1[t];
    for (int k = 0; k < 64; k++) acc += (z[k] - m - ls) * W1[t * 64 + k];
    hid[t] = fmaxf(acc, 0.f);
    __syncthreads();
    if (t < 10) {
        float o = b2[t];
        for (int k = 0; k < 128; k++) o += hid[k] * W2[t * 128 + k];
        out[n * 10 + t] = o;
    }
}

// ------------------------- launcher -----------------------------------------
extern "C" void kernel_launch(void* const* d_in, const int* in_sizes, int n_in,
                              void* d_out, int out_size) {
    const float* x      = (const float*)d_in[0];
    const float* Wrel   = (const float*)d_in[1];
    const float* brel   = (const float*)d_in[2];
    const float* Wroot  = (const float*)d_in[3];
    const float* bng    = (const float*)d_in[4];
    const float* bnb    = (const float*)d_in[5];
    const float* Wrel_s = (const float*)d_in[6];
    const float* brel_s = (const float*)d_in[7];
    const float* Wroot_s= (const float*)d_in[8];
    const float* bnsg   = (const float*)d_in[9];
    const float* bnsb   = (const float*)d_in[10];
    const float* W1     = (const float*)d_in[11];
    const float* b1     = (const float*)d_in[12];
    const float* W2     = (const float*)d_in[13];
    const float* b2     = (const float*)d_in[14];
    const int*   ei     = (const int*)d_in[15];
    const int*   oe     = (const int*)d_in[16];
    float*       out    = (float*)d_out;

    void *p_cnt, *p_hA, *p_hB, *p_agg, *p_xsum, *p_aggs, *p_y2;
    void *p_stA, *p_stS, *p_scale, *p_shift, *p_scale_s, *p_shift_s;
    cudaGetSymbolAddress(&p_cnt, g_cnt);
    cudaGetSymbolAddress(&p_hA, g_hA);
    cudaGetSymbolAddress(&p_hB, g_hB);
    cudaGetSymbolAddress(&p_agg, g_agg);
    cudaGetSymbolAddress(&p_xsum, g_xsum);
    cudaGetSymbolAddress(&p_aggs, g_aggs);
    cudaGetSymbolAddress(&p_y2, g_y2);
    cudaGetSymbolAddress(&p_stA, g_stA);
    cudaGetSymbolAddress(&p_stS, g_stS);
    cudaGetSymbolAddress(&p_scale, g_scale);
    cudaGetSymbolAddress(&p_shift, g_shift);
    cudaGetSymbolAddress(&p_scale_s, g_scale_s);
    cudaGetSymbolAddress(&p_shift_s, g_shift_s);

    // ---- CSR build ----
    cudaMemsetAsync(p_cnt, 0, NT * sizeof(int));
    k_hist<<<E_SUB / 256, 256>>>(ei + E_SUB);
    k_bsum<<<256, 256>>>();
    k_scanb<<<1, 256>>>();
    k_scanlocal<<<256, 256>>>();
    k_scatter<<<E_SUB / 256, 256>>>(ei, ei + E_SUB);

    const float* hcur = x;
    float* bufs[2] = { (float*)p_hA, (float*)p_hB };

    for (int i = 0; i < LAYERS; i++) {
        float* Y = bufs[i & 1];

        // big-graph path: aggregation + dual GEMM (stats fused)
        k_gather<<<(NT * 32) / 256, 256>>>(hcur);
        cudaMemsetAsync(p_stA, 0, 2 * D * sizeof(float));
        k_gemm2p<<<NT / 128, 256>>>((const float*)p_agg, hcur,
                                    Wrel + i * 4096, Wroot + i * 4096, brel + i * 64,
                                    Y, (float*)p_stA);
        k_finalize<<<1, 64>>>((const float*)p_stA, bng + i * 64, bnb + i * 64,
                              1.0f / (float)NT, (float*)p_scale, (float*)p_shift);

        // subgraph-level path
        cudaMemsetAsync(p_xsum, 0, NN * D * sizeof(float));
        k_xsum_partial<<<NN * 8, 64>>>(hcur);
        cudaMemsetAsync(p_aggs, 0, NN * D * sizeof(float));
        k_scatter_s<<<(EO * 64) / 256, 256>>>(oe, oe + EO);
        cudaMemsetAsync(p_stS, 0, 2 * D * sizeof(float));
        k_gemm2p<<<NN / 128, 256>>>((const float*)p_aggs, (const float*)p_xsum,
                                    Wrel_s + i * 4096, Wroot_s + i * 4096, brel_s + i * 64,
                                    (float*)p_y2, (float*)p_stS);
        k_finalize<<<1, 64>>>((const float*)p_stS, bnsg + i * 64, bnsb + i * 64,
                              1.0f / (float)NN, (float*)p_scale_s, (float*)p_shift_s);

        // fuse both BNs + broadcast + relu, in place
        k_combine<<<(NT * 16) / 256, 256>>>(Y);
        hcur = Y;
    }

    // readout: subgraph mean -> log_softmax -> MLP
    cudaMemsetAsync(p_xsum, 0, NN * D * sizeof(float));
    k_xsum_partial<<<NN * 8, 64>>>(hcur);
    k_final<<<NN, 128>>>(W1, b1, W2, b2, out);
}

// round 5
// speedup vs baseline: 1.5170x; 1.0320x over previous
#include <cuda_runtime.h>
#include <math.h>

#define NT      262144      // total nodes (512 subgraphs x 512 nodes)
#define NN      512         // nodes per subgraph / original graph
#define E_SUB   2097152     // edges in union-of-subgraphs graph
#define EO      8192        // edges in original graph
#define D       64          // emb dim
#define LAYERS  4

// ------------------------- device scratch (no cudaMalloc allowed) ----------
__device__ __align__(16) float g_hA[(size_t)NT * D];
__device__ __align__(16) float g_hB[(size_t)NT * D];
__device__ __align__(16) float g_agg[(size_t)NT * D];

__device__ __align__(16) float g_xsum[NN * D];
__device__ __align__(16) float g_aggs[NN * D];
__device__ __align__(16) float g_y2[NN * D];
__device__ __align__(16) float g_add2[NN * D];   // y2*scale_s + shift_s + shift

__device__ __align__(16) float g_stA[2 * D];
__device__ __align__(16) float g_stS[2 * D];
__device__ __align__(16) float g_scale[D],  g_shift[D];
__device__ __align__(16) float g_scale_s[D], g_shift_s[D];

__device__ int g_cnt[NT];
__device__ int g_rowptr[NT + 1];
__device__ int g_bsum[256];
__device__ int g_csrsrc[E_SUB];

// ------------------------- CSR build ---------------------------------------
__global__ void k_hist(const int* __restrict__ dst) {
    int e = blockIdx.x * blockDim.x + threadIdx.x;
    if (e < E_SUB) atomicAdd(&g_cnt[dst[e]], 1);
}

__global__ void k_bsum() {
    __shared__ int sh[256];
    int b = blockIdx.x, t = threadIdx.x;
    int base = b * 1024 + t * 4;
    int v = g_cnt[base] + g_cnt[base + 1] + g_cnt[base + 2] + g_cnt[base + 3];
    sh[t] = v;
    __syncthreads();
    for (int off = 128; off > 0; off >>= 1) {
        if (t < off) sh[t] += sh[t + off];
        __syncthreads();
    }
    if (t == 0) g_bsum[b] = sh[0];
}

__global__ void k_scanb() {
    __shared__ int sh[256];
    int t = threadIdx.x;
    int orig = g_bsum[t];
    sh[t] = orig;
    __syncthreads();
    for (int off = 1; off < 256; off <<= 1) {
        int v = (t >= off) ? sh[t - off] : 0;
        __syncthreads();
        sh[t] += v;
        __syncthreads();
    }
    g_bsum[t] = sh[t] - orig;   // exclusive
}

__global__ void k_scanlocal() {
    __shared__ int sh[256];
    int b = blockIdx.x, t = threadIdx.x;
    int base = (b * 256 + t) * 4;
    int c0 = g_cnt[base], c1 = g_cnt[base + 1], c2 = g_cnt[base + 2], c3 = g_cnt[base + 3];
    int tsum = c0 + c1 + c2 + c3;
    sh[t] = tsum;
    __syncthreads();
    for (int off = 1; off < 256; off <<= 1) {
        int v = (t >= off) ? sh[t - off] : 0;
        __syncthreads();
        sh[t] += v;
        __syncthreads();
    }
    int excl = sh[t] - tsum + g_bsum[b];
    int e0 = excl, e1 = e0 + c0, e2 = e1 + c1, e3 = e2 + c2;
    g_rowptr[base] = e0; g_rowptr[base + 1] = e1;
    g_rowptr[base + 2] = e2; g_rowptr[base + 3] = e3;
    g_cnt[base] = e0; g_cnt[base + 1] = e1;
    g_cnt[base + 2] = e2; g_cnt[base + 3] = e3;
    if (b == 255 && t == 255) g_rowptr[NT] = E_SUB;
}

__global__ void k_scatter(const int* __restrict__ src, const int* __restrict__ dst) {
    int e = blockIdx.x * blockDim.x + threadIdx.x;
    if (e < E_SUB) {
        int pos = atomicAdd(&g_cnt[dst[e]], 1);
        g_csrsrc[pos] = src[e];
    }
}

// ------------------------- smem-staged gather -------------------------------
// One block per subgraph. Stage transformed h slice (512x64 f32 = 128KB) into
// dynamic smem, then gather all edges of the subgraph from smem.
__global__ void __launch_bounds__(512)
k_gather_sm(const float* __restrict__ Y, int flag) {
    extern __shared__ float sh[];                  // [512][64]
    int g = blockIdx.x, t = threadIdx.x;
    int c4 = t & 15;

    float4 sc4 = make_float4(1.f, 1.f, 1.f, 1.f);
    if (flag) sc4 = *reinterpret_cast<const float4*>(&g_scale[c4 * 4]);

#pragma unroll
    for (int it = 0; it < 16; it++) {
        int n = it * 32 + (t >> 4);
        float4 v = reinterpret_cast<const float4*>(Y)[((size_t)g * 512 + n) * 16 + c4];
        if (flag) {
            float4 a2 = reinterpret_cast<const float4*>(g_add2)[n * 16 + c4];
            v.x = fmaxf(v.x * sc4.x + a2.x, 0.f);
            v.y = fmaxf(v.y * sc4.y + a2.y, 0.f);
            v.z = fmaxf(v.z * sc4.z + a2.z, 0.f);
            v.w = fmaxf(v.w * sc4.w + a2.w, 0.f);
        }
        reinterpret_cast<float4*>(sh)[n * 16 + c4] = v;
    }
    __syncthreads();

    int w = t >> 5, lane = t & 31;
    const float2* sh2 = reinterpret_cast<const float2*>(sh);
#pragma unroll 1
    for (int rr = 0; rr < 32; rr++) {
        int n = w * 32 + rr;
        int r = g * 512 + n;
        int s = g_rowptr[r], e = g_rowptr[r + 1];
        float2 a = make_float2(0.f, 0.f), b = make_float2(0.f, 0.f);
        int i = s;
        for (; i + 1 < e; i += 2) {
            int l0 = g_csrsrc[i] & 511, l1 = g_csrsrc[i + 1] & 511;
            float2 v0 = sh2[l0 * 32 + lane];
            float2 v1 = sh2[l1 * 32 + lane];
            a.x += v0.x; a.y += v0.y;
            b.x += v1.x; b.y += v1.y;
        }
        if (i < e) {
            int l0 = g_csrsrc[i] & 511;
            float2 v0 = sh2[l0 * 32 + lane];
            a.x += v0.x; a.y += v0.y;
        }
        reinterpret_cast<float2*>(g_agg)[(size_t)r * 32 + lane] =
            make_float2(a.x + b.x, a.y + b.y);
    }
}

// ------------------------- dual GEMM (R1 structure) + transform + stats -----
// Y[r][c] = sum_k A0[r][k]*W0[c][k] + A1'[r][k]*W1[c][k] + bias[c]
// A1' = flag ? relu(A1*scale + add2[n]) : A1   (n = row & 511)
__global__ void __launch_bounds__(256)
k_gemmR(const float* __restrict__ A0, const float* __restrict__ A1,
        const float* __restrict__ W0, const float* __restrict__ W1v,
        const float* __restrict__ bias, float* __restrict__ Y,
        float* __restrict__ st, int flag) {
    __shared__ __align__(16) float sA[64][65];   // sA[k][row]
    __shared__ __align__(16) float sW[64][68];   // sW[k][col]
    int t  = threadIdx.x;
    int tx = t & 15, ty = t >> 4;
    int row0 = blockIdx.x * 64;
    int cc = t & 63, rb = t >> 6;

    float scl = flag ? g_scale[cc] : 1.0f;

    float acc[4][4];
#pragma unroll
    for (int i = 0; i < 4; i++)
#pragma unroll
        for (int j = 0; j < 4; j++) acc[i][j] = 0.f;

    for (int p = 0; p < 2; p++) {
        const float* A = p ? A1 : A0;
        const float* W = p ? W1v : W0;
#pragma unroll
        for (int j = 0; j < 16; j++) {
            int r = rb + j * 4;
            float a = A[(size_t)(row0 + r) * D + cc];
            if (p && flag)
                a = fmaxf(a * scl + g_add2[((row0 + r) & 511) * D + cc], 0.f);
            sA[cc][r] = a;
        }
#pragma unroll
        for (int j = 0; j < 16; j++) {
            int ci = rb + j * 4;
            sW[cc][ci] = W[ci * D + cc];
        }
        __syncthreads();
#pragma unroll
        for (int k = 0; k < 64; k++) {
            float4 bv = *reinterpret_cast<const float4*>(&sW[k][tx * 4]);
            float a0 = sA[k][ty * 4 + 0];
            float a1 = sA[k][ty * 4 + 1];
            float a2 = sA[k][ty * 4 + 2];
            float a3 = sA[k][ty * 4 + 3];
            acc[0][0] += a0 * bv.x; acc[0][1] += a0 * bv.y; acc[0][2] += a0 * bv.z; acc[0][3] += a0 * bv.w;
            acc[1][0] += a1 * bv.x; acc[1][1] += a1 * bv.y; acc[1][2] += a1 * bv.z; acc[1][3] += a1 * bv.w;
            acc[2][0] += a2 * bv.x; acc[2][1] += a2 * bv.y; acc[2][2] += a2 * bv.z; acc[2][3] += a2 * bv.w;
            acc[3][0] += a3 * bv.x; acc[3][1] += a3 * bv.y; acc[3][2] += a3 * bv.z; acc[3][3] += a3 * bv.w;
        }
        __syncthreads();
    }

    // epilogue: bias, write, per-thread BN stat partials
    float4 bb = *reinterpret_cast<const float4*>(&bias[tx * 4]);
    float bcol[4] = { bb.x, bb.y, bb.z, bb.w };
    float ls[4] = {0.f, 0.f, 0.f, 0.f};
    float lq[4] = {0.f, 0.f, 0.f, 0.f};
#pragma unroll
    for (int jr = 0; jr < 4; jr++) {
        float y0 = acc[jr][0] + bcol[0];
        float y1 = acc[jr][1] + bcol[1];
        float y2 = acc[jr][2] + bcol[2];
        float y3 = acc[jr][3] + bcol[3];
        ls[0] += y0; ls[1] += y1; ls[2] += y2; ls[3] += y3;
        lq[0] += y0 * y0; lq[1] += y1 * y1; lq[2] += y2 * y2; lq[3] += y3 * y3;
        int r = row0 + ty * 4 + jr;
        *reinterpret_cast<float4*>(&Y[(size_t)r * D + tx * 4]) =
            make_float4(y0, y1, y2, y3);
    }

    // block reduction of column sums / sumsq (reuse sA flat)
    float* rs = &sA[0][0];          // 1024 floats
    float* rq = rs + 1024;          // 1024 floats (sA has 4160)
#pragma unroll
    for (int j = 0; j < 4; j++) {
        rs[ty * 64 + tx * 4 + j] = ls[j];
        rq[ty * 64 + tx * 4 + j] = lq[j];
    }
    __syncthreads();
    if (t < 64) {
        float s = 0.f, q = 0.f;
#pragma unroll
        for (int g = 0; g < 16; g++) {
            s += rs[g * 64 + t];
            q += rq[g * 64 + t];
        }
        atomicAdd(&st[t], s);
        atomicAdd(&st[64 + t], q);
    }
}

// ------------------------- BN finalize --------------------------------------
__global__ void k_finalize(const float* __restrict__ st,
                           const float* __restrict__ gamma, const float* __restrict__ beta,
                           float inv, float* __restrict__ scale, float* __restrict__ shift) {
    int t = threadIdx.x;
    float mean = st[t] * inv;
    float var  = st[64 + t] * inv - mean * mean;
    float is   = rsqrtf(var + 1e-5f);
    float sc   = gamma[t] * is;
    scale[t] = sc;
    shift[t] = beta[t] - mean * sc;
}

// ---- add2 = y2*scale_s + shift_s + shift  (full additive part of combine) --
__global__ void k_add2() {
    int idx = blockIdx.x * blockDim.x + threadIdx.x;   // < NN*D = 32768
    int c = idx & 63;
    g_add2[idx] = g_y2[idx] * g_scale_s[c] + g_shift_s[c] + g_shift[c];
}

// ------------------------- subgraph mean (with inline transform) ------------
__global__ void k_xsum_partial(const float* __restrict__ Y, int flag) {
    int n  = blockIdx.x & (NN - 1);
    int sg = blockIdx.x >> 9;
    int c  = threadIdx.x;
    float scl = flag ? g_scale[c] : 1.0f;
    float a2  = flag ? g_add2[n * D + c] : 0.0f;
    float a0 = 0.f, a1 = 0.f;
#pragma unroll 4
    for (int j = 0; j < 64; j += 2) {
        int s = sg * 64 + j;
        float v0 = Y[((size_t)(s + 0) * NN + n) * D + c];
        float v1 = Y[((size_t)(s + 1) * NN + n) * D + c];
        if (flag) {
            v0 = fmaxf(v0 * scl + a2, 0.f);
            v1 = fmaxf(v1 * scl + a2, 0.f);
        }
        a0 += v0; a1 += v1;
    }
    atomicAdd(&g_xsum[n * D + c], (a0 + a1) * (1.0f / 512.0f));
}

// ------------------------- small graph scatter ------------------------------
__global__ void k_scatter_s(const int* __restrict__ src, const int* __restrict__ dst) {
    int t = blockIdx.x * blockDim.x + threadIdx.x;
    int e = t >> 6, c = t & 63;
    if (e < EO) atomicAdd(&g_aggs[dst[e] * D + c], g_xsum[src[e] * D + c]);
}

// ------------------------- final head: log_softmax + MLP -------------------
__global__ void k_final(const float* __restrict__ W1, const float* __restrict__ b1,
                        const float* __restrict__ W2, const float* __restrict__ b2,
                        float* __restrict__ out) {
    __shared__ float z[64];
    __shared__ float hid[128];
    __shared__ float red[2];
    int n = blockIdx.x, t = threadIdx.x;
    if (t < 64) z[t] = g_xsum[n * D + t];
    __syncthreads();
    if (t == 0) {
        float m = -1e30f;
        for (int k = 0; k < 64; k++) m = fmaxf(m, z[k]);
        float se = 0.f;
        for (int k = 0; k < 64; k++) se += expf(z[k] - m);
        red[0] = m;
        red[1] = logf(se);
    }
    __syncthreads();
    float m = red[0], ls = red[1];
    float acc = b1[t];
    for (int k = 0; k < 64; k++) acc += (z[k] - m - ls) * W1[t * 64 + k];
    hid[t] = fmaxf(acc, 0.f);
    __syncthreads();
    if (t < 10) {
        float o = b2[t];
        for (int k = 0; k < 128; k++) o += hid[k] * W2[t * 128 + k];
        out[n * 10 + t] = o;
    }
}

// ------------------------- launcher -----------------------------------------
extern "C" void kernel_launch(void* const* d_in, const int* in_sizes, int n_in,
                              void* d_out, int out_size) {
    const float* x      = (const float*)d_in[0];
    const float* Wrel   = (const float*)d_in[1];
    const float* brel   = (const float*)d_in[2];
    const float* Wroot  = (const float*)d_in[3];
    const float* bng    = (const float*)d_in[4];
    const float* bnb    = (const float*)d_in[5];
    const float* Wrel_s = (const float*)d_in[6];
    const float* brel_s = (const float*)d_in[7];
    const float* Wroot_s= (const float*)d_in[8];
    const float* bnsg   = (const float*)d_in[9];
    const float* bnsb   = (const float*)d_in[10];
    const float* W1     = (const float*)d_in[11];
    const float* b1     = (const float*)d_in[12];
    const float* W2     = (const float*)d_in[13];
    const float* b2     = (const float*)d_in[14];
    const int*   ei     = (const int*)d_in[15];
    const int*   oe     = (const int*)d_in[16];
    float*       out    = (float*)d_out;

    // 128KB dynamic smem opt-in (host-side attribute, not a stream op; safe
    // under capture, deterministic, called every time — no static guards).
    cudaFuncSetAttribute(k_gather_sm,
                         cudaFuncAttributeMaxDynamicSharedMemorySize, 131072);

    void *p_cnt, *p_hA, *p_hB, *p_agg, *p_xsum, *p_aggs, *p_y2;
    void *p_stA, *p_stS, *p_scale, *p_shift, *p_scale_s, *p_shift_s;
    cudaGetSymbolAddress(&p_cnt, g_cnt);
    cudaGetSymbolAddress(&p_hA, g_hA);
    cudaGetSymbolAddress(&p_hB, g_hB);
    cudaGetSymbolAddress(&p_agg, g_agg);
    cudaGetSymbolAddress(&p_xsum, g_xsum);
    cudaGetSymbolAddress(&p_aggs, g_aggs);
    cudaGetSymbolAddress(&p_y2, g_y2);
    cudaGetSymbolAddress(&p_stA, g_stA);
    cudaGetSymbolAddress(&p_stS, g_stS);
    cudaGetSymbolAddress(&p_scale, g_scale);
    cudaGetSymbolAddress(&p_shift, g_shift);
    cudaGetSymbolAddress(&p_scale_s, g_scale_s);
    cudaGetSymbolAddress(&p_shift_s, g_shift_s);

    // ---- CSR build ----
    cudaMemsetAsync(p_cnt, 0, NT * sizeof(int));
    k_hist<<<E_SUB / 256, 256>>>(ei + E_SUB);
    k_bsum<<<256, 256>>>();
    k_scanb<<<1, 256>>>();
    k_scanlocal<<<256, 256>>>();
    k_scatter<<<E_SUB / 256, 256>>>(ei, ei + E_SUB);

    const float* hsrc = x;
    float* bufs[2] = { (float*)p_hA, (float*)p_hB };

    for (int i = 0; i < LAYERS; i++) {
        float* Y = bufs[i & 1];
        int flag = (i > 0) ? 1 : 0;

        // aggregation over subgraph edges (transform applied while staging)
        k_gather_sm<<<NN, 512, 131072>>>(hsrc, flag);

        // big dual GEMM (A1 transformed inline), fused BN stats
        cudaMemsetAsync(p_stA, 0, 2 * D * sizeof(float));
        k_gemmR<<<NT / 64, 256>>>((const float*)p_agg, hsrc,
                                  Wrel + i * 4096, Wroot + i * 4096, brel + i * 64,
                                  Y, (float*)p_stA, flag);

        // subgraph-level path (reads prev-transformed h)
        cudaMemsetAsync(p_xsum, 0, NN * D * sizeof(float));
        k_xsum_partial<<<NN * 8, 64>>>(hsrc, flag);
        cudaMemsetAsync(p_aggs, 0, NN * D * sizeof(float));
        k_scatter_s<<<(EO * 64) / 256, 256>>>(oe, oe + EO);
        cudaMemsetAsync(p_stS, 0, 2 * D * sizeof(float));
        k_gemmR<<<NN / 64, 256>>>((const float*)p_aggs, (const float*)p_xsum,
                                  Wrel_s + i * 4096, Wroot_s + i * 4096, brel_s + i * 64,
                                  (float*)p_y2, (float*)p_stS, 0);

        // compute this layer's transform (prev transform fully consumed above)
        k_finalize<<<1, 64>>>((const float*)p_stA, bng + i * 64, bnb + i * 64,
                              1.0f / (float)NT, (float*)p_scale, (float*)p_shift);
        k_finalize<<<1, 64>>>((const float*)p_stS, bnsg + i * 64, bnsb + i * 64,
                              1.0f / (float)NN, (float*)p_scale_s, (float*)p_shift_s);
        k_add2<<<NN * D / 256, 256>>>();

        hsrc = Y;   // pre-transform output; consumers apply (scale, add2)
    }

    // readout: subgraph mean of final transformed h -> log_softmax -> MLP
    cudaMemsetAsync(p_xsum, 0, NN * D * sizeof(float));
    k_xsum_partial<<<NN * 8, 64>>>(hsrc, 1);
    k_final<<<NN, 128>>>(W1, b1, W2, b2, out);
}

// round 6
// speedup vs baseline: 1.5459x; 1.0191x over previous
#include <cuda_runtime.h>
#include <math.h>

#define NT      262144      // total nodes (512 subgraphs x 512 nodes)
#define NN      512         // nodes per subgraph / original graph
#define E_SUB   2097152     // edges in union-of-subgraphs graph
#define EO      8192        // edges in original graph
#define D       64          // emb dim
#define LAYERS  4
#define ECAP    6144        // staged edge-index capacity per subgraph (mean 4096, sd 64)

// dynamic smem: data tile + edge indices + rowptr slice
#define SM_BYTES (512 * 64 * 4 + ECAP * 4 + 516 * 4)

// ------------------------- device scratch (no cudaMalloc allowed) ----------
__device__ __align__(16) float g_hA[(size_t)NT * D];
__device__ __align__(16) float g_hB[(size_t)NT * D];
__device__ __align__(16) float g_agg[(size_t)NT * D];

__device__ __align__(16) float g_xsum[NN * D];
__device__ __align__(16) float g_aggs[NN * D];
__device__ __align__(16) float g_y2[NN * D];
__device__ __align__(16) float g_add2[NN * D];   // y2*scale_s + shift_s + shift

__device__ __align__(16) float g_stA[2 * D];
__device__ __align__(16) float g_stS[2 * D];
__device__ __align__(16) float g_scale[D],  g_shift[D];
__device__ __align__(16) float g_scale_s[D], g_shift_s[D];

__device__ int g_cnt[NT];
__device__ int g_rowptr[NT + 1];
__device__ int g_bsum[256];
__device__ int g_csrsrc[E_SUB];

// ------------------------- CSR build ---------------------------------------
__global__ void k_hist(const int* __restrict__ dst) {
    int e = blockIdx.x * blockDim.x + threadIdx.x;
    if (e < E_SUB) atomicAdd(&g_cnt[dst[e]], 1);
}

__global__ void k_bsum() {
    __shared__ int sh[256];
    int b = blockIdx.x, t = threadIdx.x;
    int base = b * 1024 + t * 4;
    int v = g_cnt[base] + g_cnt[base + 1] + g_cnt[base + 2] + g_cnt[base + 3];
    sh[t] = v;
    __syncthreads();
    for (int off = 128; off > 0; off >>= 1) {
        if (t < off) sh[t] += sh[t + off];
        __syncthreads();
    }
    if (t == 0) g_bsum[b] = sh[0];
}

__global__ void k_scanb() {
    __shared__ int sh[256];
    int t = threadIdx.x;
    int orig = g_bsum[t];
    sh[t] = orig;
    __syncthreads();
    for (int off = 1; off < 256; off <<= 1) {
        int v = (t >= off) ? sh[t - off] : 0;
        __syncthreads();
        sh[t] += v;
        __syncthreads();
    }
    g_bsum[t] = sh[t] - orig;   // exclusive
}

__global__ void k_scanlocal() {
    __shared__ int sh[256];
    int b = blockIdx.x, t = threadIdx.x;
    int base = (b * 256 + t) * 4;
    int c0 = g_cnt[base], c1 = g_cnt[base + 1], c2 = g_cnt[base + 2], c3 = g_cnt[base + 3];
    int tsum = c0 + c1 + c2 + c3;
    sh[t] = tsum;
    __syncthreads();
    for (int off = 1; off < 256; off <<= 1) {
        int v = (t >= off) ? sh[t - off] : 0;
        __syncthreads();
        sh[t] += v;
        __syncthreads();
    }
    int excl = sh[t] - tsum + g_bsum[b];
    int e0 = excl, e1 = e0 + c0, e2 = e1 + c1, e3 = e2 + c2;
    g_rowptr[base] = e0; g_rowptr[base + 1] = e1;
    g_rowptr[base + 2] = e2; g_rowptr[base + 3] = e3;
    g_cnt[base] = e0; g_cnt[base + 1] = e1;
    g_cnt[base + 2] = e2; g_cnt[base + 3] = e3;
    if (b == 255 && t == 255) g_rowptr[NT] = E_SUB;
}

__global__ void k_scatter(const int* __restrict__ src, const int* __restrict__ dst) {
    int e = blockIdx.x * blockDim.x + threadIdx.x;
    if (e < E_SUB) {
        int pos = atomicAdd(&g_cnt[dst[e]], 1);
        g_csrsrc[pos] = src[e];
    }
}

// ------------------------- smem-staged gather v2 -----------------------------
// One block per subgraph. Stage transformed h slice (128KB), edge indices
// (<=ECAP) and the rowptr slice into smem; inner loop touches smem only.
__global__ void __launch_bounds__(512)
k_gather_sm(const float* __restrict__ Y, int flag) {
    extern __shared__ float smem[];
    float* sh  = smem;                               // [512][64]
    int* sIdx  = (int*)(smem + 512 * 64);            // [ECAP]
    int* sRp   = sIdx + ECAP;                        // [513]

    int g = blockIdx.x, t = threadIdx.x;
    int c4 = t & 15;

    // stage rowptr slice + edge indices
    int e0 = g_rowptr[g * 512];
    int e1 = g_rowptr[(g + 1) * 512];
    int cnt = e1 - e0;
    if (t < 513) {
        // 513 <= 512? no: handle 513th separately
        sRp[t] = g_rowptr[g * 512 + t] - e0;
    }
    if (t == 0) sRp[512] = cnt;
    int lim = cnt < ECAP ? cnt : ECAP;
    for (int i = t; i < lim; i += 512)
        sIdx[i] = g_csrsrc[e0 + i] & 511;

    // stage (transformed) data tile
    float4 sc4 = make_float4(1.f, 1.f, 1.f, 1.f);
    if (flag) sc4 = *reinterpret_cast<const float4*>(&g_scale[c4 * 4]);
#pragma unroll
    for (int it = 0; it < 16; it++) {
        int n = it * 32 + (t >> 4);
        float4 v = reinterpret_cast<const float4*>(Y)[((size_t)g * 512 + n) * 16 + c4];
        if (flag) {
            float4 a2 = reinterpret_cast<const float4*>(g_add2)[n * 16 + c4];
            v.x = fmaxf(v.x * sc4.x + a2.x, 0.f);
            v.y = fmaxf(v.y * sc4.y + a2.y, 0.f);
            v.z = fmaxf(v.z * sc4.z + a2.z, 0.f);
            v.w = fmaxf(v.w * sc4.w + a2.w, 0.f);
        }
        reinterpret_cast<float4*>(sh)[n * 16 + c4] = v;
    }
    __syncthreads();

    int w = t >> 5, lane = t & 31;
    const float2* sh2 = reinterpret_cast<const float2*>(sh);
#pragma unroll 1
    for (int rr = 0; rr < 32; rr++) {
        int n = w * 32 + rr;
        int s = sRp[n], e = sRp[n + 1];
        float2 a = make_float2(0.f, 0.f), b = make_float2(0.f, 0.f);
        int i = s;
        for (; i + 1 < e; i += 2) {
            int l0 = (i     < ECAP) ? sIdx[i]     : (g_csrsrc[e0 + i] & 511);
            int l1 = (i + 1 < ECAP) ? sIdx[i + 1] : (g_csrsrc[e0 + i + 1] & 511);
            float2 v0 = sh2[l0 * 32 + lane];
            float2 v1 = sh2[l1 * 32 + lane];
            a.x += v0.x; a.y += v0.y;
            b.x += v1.x; b.y += v1.y;
        }
        if (i < e) {
            int l0 = (i < ECAP) ? sIdx[i] : (g_csrsrc[e0 + i] & 511);
            float2 v0 = sh2[l0 * 32 + lane];
            a.x += v0.x; a.y += v0.y;
        }
        reinterpret_cast<float2*>(g_agg)[(size_t)(g * 512 + n) * 32 + lane] =
            make_float2(a.x + b.x, a.y + b.y);
    }
}

// ------------------------- dual GEMM (R1 structure) + transform + stats -----
// Y[r][c] = sum_k A0[r][k]*W0[c][k] + A1'[r][k]*W1[c][k] + bias[c]
// A1' = flag ? relu(A1*scale + add2[n]) : A1   (n = row & 511)
__global__ void __launch_bounds__(256)
k_gemmR(const float* __restrict__ A0, const float* __restrict__ A1,
        const float* __restrict__ W0, const float* __restrict__ W1v,
        const float* __restrict__ bias, float* __restrict__ Y,
        float* __restrict__ st, int flag) {
    __shared__ __align__(16) float sA[64][65];   // sA[k][row]
    __shared__ __align__(16) float sW[64][68];   // sW[k][col]
    int t  = threadIdx.x;
    int tx = t & 15, ty = t >> 4;
    int row0 = blockIdx.x * 64;
    int cc = t & 63, rb = t >> 6;

    float scl = flag ? g_scale[cc] : 1.0f;

    float acc[4][4];
#pragma unroll
    for (int i = 0; i < 4; i++)
#pragma unroll
        for (int j = 0; j < 4; j++) acc[i][j] = 0.f;

    for (int p = 0; p < 2; p++) {
        const float* A = p ? A1 : A0;
        const float* W = p ? W1v : W0;
#pragma unroll
        for (int j = 0; j < 16; j++) {
            int r = rb + j * 4;
            float a = A[(size_t)(row0 + r) * D + cc];
            if (p && flag)
                a = fmaxf(a * scl + g_add2[((row0 + r) & 511) * D + cc], 0.f);
            sA[cc][r] = a;
        }
#pragma unroll
        for (int j = 0; j < 16; j++) {
            int ci = rb + j * 4;
            sW[cc][ci] = W[ci * D + cc];
        }
        __syncthreads();
#pragma unroll
        for (int k = 0; k < 64; k++) {
            float4 bv = *reinterpret_cast<const float4*>(&sW[k][tx * 4]);
            float a0 = sA[k][ty * 4 + 0];
            float a1 = sA[k][ty * 4 + 1];
            float a2 = sA[k][ty * 4 + 2];
            float a3 = sA[k][ty * 4 + 3];
            acc[0][0] += a0 * bv.x; acc[0][1] += a0 * bv.y; acc[0][2] += a0 * bv.z; acc[0][3] += a0 * bv.w;
            acc[1][0] += a1 * bv.x; acc[1][1] += a1 * bv.y; acc[1][2] += a1 * bv.z; acc[1][3] += a1 * bv.w;
            acc[2][0] += a2 * bv.x; acc[2][1] += a2 * bv.y; acc[2][2] += a2 * bv.z; acc[2][3] += a2 * bv.w;
            acc[3][0] += a3 * bv.x; acc[3][1] += a3 * bv.y; acc[3][2] += a3 * bv.z; acc[3][3] += a3 * bv.w;
        }
        __syncthreads();
    }

    // epilogue: bias, write, per-thread BN stat partials
    float4 bb = *reinterpret_cast<const float4*>(&bias[tx * 4]);
    float bcol[4] = { bb.x, bb.y, bb.z, bb.w };
    float ls[4] = {0.f, 0.f, 0.f, 0.f};
    float lq[4] = {0.f, 0.f, 0.f, 0.f};
#pragma unroll
    for (int jr = 0; jr < 4; jr++) {
        float y0 = acc[jr][0] + bcol[0];
        float y1 = acc[jr][1] + bcol[1];
        float y2 = acc[jr][2] + bcol[2];
        float y3 = acc[jr][3] + bcol[3];
        ls[0] += y0; ls[1] += y1; ls[2] += y2; ls[3] += y3;
        lq[0] += y0 * y0; lq[1] += y1 * y1; lq[2] += y2 * y2; lq[3] += y3 * y3;
        int r = row0 + ty * 4 + jr;
        *reinterpret_cast<float4*>(&Y[(size_t)r * D + tx * 4]) =
            make_float4(y0, y1, y2, y3);
    }

    // block reduction of column sums / sumsq (reuse sA flat)
    float* rs = &sA[0][0];          // 1024 floats
    float* rq = rs + 1024;          // 1024 floats (sA has 4160)
#pragma unroll
    for (int j = 0; j < 4; j++) {
        rs[ty * 64 + tx * 4 + j] = ls[j];
        rq[ty * 64 + tx * 4 + j] = lq[j];
    }
    __syncthreads();
    if (t < 64) {
        float s = 0.f, q = 0.f;
#pragma unroll
        for (int g = 0; g < 16; g++) {
            s += rs[g * 64 + t];
            q += rq[g * 64 + t];
        }
        atomicAdd(&st[t], s);
        atomicAdd(&st[64 + t], q);
    }
}

// ------------------------- BN finalize --------------------------------------
__global__ void k_finalize(const float* __restrict__ st,
                           const float* __restrict__ gamma, const float* __restrict__ beta,
                           float inv, float* __restrict__ scale, float* __restrict__ shift) {
    int t = threadIdx.x;
    float mean = st[t] * inv;
    float var  = st[64 + t] * inv - mean * mean;
    float is   = rsqrtf(var + 1e-5f);
    float sc   = gamma[t] * is;
    scale[t] = sc;
    shift[t] = beta[t] - mean * sc;
}

// ---- add2 = y2*scale_s + shift_s + shift  (full additive part of combine) --
__global__ void k_add2() {
    int idx = blockIdx.x * blockDim.x + threadIdx.x;   // < NN*D = 32768
    int c = idx & 63;
    g_add2[idx] = g_y2[idx] * g_scale_s[c] + g_shift_s[c] + g_shift[c];
}

// ------------------------- subgraph mean (with inline transform) ------------
__global__ void k_xsum_partial(const float* __restrict__ Y, int flag) {
    int n  = blockIdx.x & (NN - 1);
    int sg = blockIdx.x >> 9;
    int c  = threadIdx.x;
    float scl = flag ? g_scale[c] : 1.0f;
    float a2  = flag ? g_add2[n * D + c] : 0.0f;
    float a0 = 0.f, a1 = 0.f;
#pragma unroll 4
    for (int j = 0; j < 64; j += 2) {
        int s = sg * 64 + j;
        float v0 = Y[((size_t)(s + 0) * NN + n) * D + c];
        float v1 = Y[((size_t)(s + 1) * NN + n) * D + c];
        if (flag) {
            v0 = fmaxf(v0 * scl + a2, 0.f);
            v1 = fmaxf(v1 * scl + a2, 0.f);
        }
        a0 += v0; a1 += v1;
    }
    atomicAdd(&g_xsum[n * D + c], (a0 + a1) * (1.0f / 512.0f));
}

// ------------------------- small graph scatter ------------------------------
__global__ void k_scatter_s(const int* __restrict__ src, const int* __restrict__ dst) {
    int t = blockIdx.x * blockDim.x + threadIdx.x;
    int e = t >> 6, c = t & 63;
    if (e < EO) atomicAdd(&g_aggs[dst[e] * D + c], g_xsum[src[e] * D + c]);
}

// ------------------------- final head: log_softmax + MLP -------------------
__global__ void k_final(const float* __restrict__ W1, const float* __restrict__ b1,
                        const float* __restrict__ W2, const float* __restrict__ b2,
                        float* __restrict__ out) {
    __shared__ float z[64];
    __shared__ float hid[128];
    __shared__ float red[2];
    int n = blockIdx.x, t = threadIdx.x;
    if (t < 64) z[t] = g_xsum[n * D + t];
    __syncthreads();
    if (t == 0) {
        float m = -1e30f;
        for (int k = 0; k < 64; k++) m = fmaxf(m, z[k]);
        float se = 0.f;
        for (int k = 0; k < 64; k++) se += expf(z[k] - m);
        red[0] = m;
        red[1] = logf(se);
    }
    __syncthreads();
    float m = red[0], ls = red[1];
    float acc = b1[t];
    for (int k = 0; k < 64; k++) acc += (z[k] - m - ls) * W1[t * 64 + k];
    hid[t] = fmaxf(acc, 0.f);
    __syncthreads();
    if (t < 10) {
        float o = b2[t];
        for (int k = 0; k < 128; k++) o += hid[k] * W2[t * 128 + k];
        out[n * 10 + t] = o;
    }
}

// ------------------------- launcher -----------------------------------------
extern "C" void kernel_launch(void* const* d_in, const int* in_sizes, int n_in,
                              void* d_out, int out_size) {
    const float* x      = (const float*)d_in[0];
    const float* Wrel   = (const float*)d_in[1];
    const float* brel   = (const float*)d_in[2];
    const float* Wroot  = (const float*)d_in[3];
    const float* bng    = (const float*)d_in[4];
    const float* bnb    = (const float*)d_in[5];
    const float* Wrel_s = (const float*)d_in[6];
    const float* brel_s = (const float*)d_in[7];
    const float* Wroot_s= (const float*)d_in[8];
    const float* bnsg   = (const float*)d_in[9];
    const float* bnsb   = (const float*)d_in[10];
    const float* W1     = (const float*)d_in[11];
    const float* b1     = (const float*)d_in[12];
    const float* W2     = (const float*)d_in[13];
    const float* b2     = (const float*)d_in[14];
    const int*   ei     = (const int*)d_in[15];
    const int*   oe     = (const int*)d_in[16];
    float*       out    = (float*)d_out;

    // dynamic smem opt-in (host attribute; capture-safe; no static guards)
    cudaFuncSetAttribute(k_gather_sm,
                         cudaFuncAttributeMaxDynamicSharedMemorySize, SM_BYTES);

    void *p_cnt, *p_hA, *p_hB, *p_agg, *p_xsum, *p_aggs, *p_y2;
    void *p_stA, *p_stS, *p_scale, *p_shift, *p_scale_s, *p_shift_s;
    cudaGetSymbolAddress(&p_cnt, g_cnt);
    cudaGetSymbolAddress(&p_hA, g_hA);
    cudaGetSymbolAddress(&p_hB, g_hB);
    cudaGetSymbolAddress(&p_agg, g_agg);
    cudaGetSymbolAddress(&p_xsum, g_xsum);
    cudaGetSymbolAddress(&p_aggs, g_aggs);
    cudaGetSymbolAddress(&p_y2, g_y2);
    cudaGetSymbolAddress(&p_stA, g_stA);
    cudaGetSymbolAddress(&p_stS, g_stS);
    cudaGetSymbolAddress(&p_scale, g_scale);
    cudaGetSymbolAddress(&p_shift, g_shift);
    cudaGetSymbolAddress(&p_scale_s, g_scale_s);
    cudaGetSymbolAddress(&p_shift_s, g_shift_s);

    // ---- CSR build ----
    cudaMemsetAsync(p_cnt, 0, NT * sizeof(int));
    k_hist<<<E_SUB / 256, 256>>>(ei + E_SUB);
    k_bsum<<<256, 256>>>();
    k_scanb<<<1, 256>>>();
    k_scanlocal<<<256, 256>>>();
    k_scatter<<<E_SUB / 256, 256>>>(ei, ei + E_SUB);

    const float* hsrc = x;
    float* bufs[2] = { (float*)p_hA, (float*)p_hB };

    for (int i = 0; i < LAYERS; i++) {
        float* Y = bufs[i & 1];
        int flag = (i > 0) ? 1 : 0;

        // aggregation over subgraph edges (transform applied while staging)
        k_gather_sm<<<NN, 512, SM_BYTES>>>(hsrc, flag);

        // big dual GEMM (A1 transformed inline), fused BN stats
        cudaMemsetAsync(p_stA, 0, 2 * D * sizeof(float));
        k_gemmR<<<NT / 64, 256>>>((const float*)p_agg, hsrc,
                                  Wrel + i * 4096, Wroot + i * 4096, brel + i * 64,
                                  Y, (float*)p_stA, flag);

        // subgraph-level path (reads prev-transformed h)
        cudaMemsetAsync(p_xsum, 0, NN * D * sizeof(float));
        k_xsum_partial<<<NN * 8, 64>>>(hsrc, flag);
        cudaMemsetAsync(p_aggs, 0, NN * D * sizeof(float));
        k_scatter_s<<<(EO * 64) / 256, 256>>>(oe, oe + EO);
        cudaMemsetAsync(p_stS, 0, 2 * D * sizeof(float));
        k_gemmR<<<NN / 64, 256>>>((const float*)p_aggs, (const float*)p_xsum,
                                  Wrel_s + i * 4096, Wroot_s + i * 4096, brel_s + i * 64,
                                  (float*)p_y2, (float*)p_stS, 0);

        // compute this layer's transform (prev transform fully consumed above)
        k_finalize<<<1, 64>>>((const float*)p_stA, bng + i * 64, bnb + i * 64,
                              1.0f / (float)NT, (float*)p_scale, (float*)p_shift);
        k_finalize<<<1, 64>>>((const float*)p_stS, bnsg + i * 64, bnsb + i * 64,
                              1.0f / (float)NN, (float*)p_scale_s, (float*)p_shift_s);
        k_add2<<<NN * D / 256, 256>>>();

        hsrc = Y;   // pre-transform output; consumers apply (scale, add2)
    }

    // readout: subgraph mean of final transformed h -> log_softmax -> MLP
    cudaMemsetAsync(p_xsum, 0, NN * D * sizeof(float));
    k_xsum_partial<<<NN * 8, 64>>>(hsrc, 1);
    k_final<<<NN, 128>>>(W1, b1, W2, b2, out);
}